// round 1
// baseline (speedup 1.0000x reference)
#include <cuda_runtime.h>

#define NUM_EMB 16384
#define BT      16384
#define D       64
#define NSPLIT  4
#define CODES_PER_SPLIT (NUM_EMB / NSPLIT)   // 4096
#define CHUNK   128                          // codes staged in smem per iteration
#define TOK_PER_BLK 128

// ---------------- scratch (no allocations allowed) ----------------
__device__ float g_qcb[NUM_EMB * D];    // projected codebook (unnormalized)
__device__ float g_cn [NUM_EMB * D];    // l2-normalized projected codebook
__device__ float g_bestval[NSPLIT * BT];
__device__ int   g_bestidx[NSPLIT * BT];
__device__ int   g_idx[BT];
__device__ float g_partials[128];

// ---------------- packed f32x2 helpers (sm_100+ PTX) ----------------
__device__ __forceinline__ unsigned long long fma2(unsigned long long a,
                                                   unsigned long long b,
                                                   unsigned long long c) {
    unsigned long long d;
    asm("fma.rn.f32x2 %0, %1, %2, %3;" : "=l"(d) : "l"(a), "l"(b), "l"(c));
    return d;
}
__device__ __forceinline__ unsigned long long add2(unsigned long long a,
                                                   unsigned long long b) {
    unsigned long long d;
    asm("add.rn.f32x2 %0, %1, %2;" : "=l"(d) : "l"(a), "l"(b));
    return d;
}
__device__ __forceinline__ unsigned long long pack2(float lo, float hi) {
    return ((unsigned long long)__float_as_uint(hi) << 32) |
           (unsigned long long)__float_as_uint(lo);
}

// ---------------- Kernel A: qcb = codebook @ W^T + b; cn = l2norm(qcb) ---------
// 256 blocks x 256 threads, 64 codebook rows per block.
__global__ void __launch_bounds__(256) kA(const float* __restrict__ cb,
                                          const float* __restrict__ pw,
                                          const float* __restrict__ pb) {
    __shared__ float pwT[64 * 64];   // pwT[k][c] = proj_w[c][k]
    __shared__ float qs [64 * 64];
    __shared__ float rnorm[64];
    const int tid = threadIdx.x;

    for (int i = tid; i < 4096; i += 256) {
        int c = i >> 6, k = i & 63;
        pwT[k * 64 + c] = pw[i];     // pw is row-major [out=c][in=k]
    }
    __syncthreads();

    const int c  = tid & 63;
    const int rg = tid >> 6;         // 4 row groups of 16 rows
    const float bias = pb[c];

    for (int rr = 0; rr < 16; rr++) {
        int lrow = rg * 16 + rr;
        int row  = blockIdx.x * 64 + lrow;
        const float* cbr = cb + row * 64;
        float acc = bias;
#pragma unroll
        for (int k = 0; k < 64; k++)
            acc = fmaf(__ldg(cbr + k), pwT[k * 64 + c], acc);
        qs[lrow * 64 + c] = acc;
    }
    __syncthreads();

    if (tid < 64) {
        float s = 0.f;
#pragma unroll
        for (int k = 0; k < 64; k++) {
            float v = qs[tid * 64 + k];
            s = fmaf(v, v, s);
        }
        rnorm[tid] = fmaxf(sqrtf(s), 1e-12f);
    }
    __syncthreads();

    const int base = blockIdx.x * 4096;
    for (int i = tid; i < 4096; i += 256) {
        float v = qs[i];
        g_qcb[base + i] = v;
        g_cn [base + i] = v / rnorm[i >> 6];
    }
}

// ---------------- Kernel B: per-token argmax over a code split -------------
// grid (128 token-blocks, 4 code-splits), 128 threads; 1 token per thread,
// token vector in registers, code tile broadcast from smem, f32x2 FMAs.
__global__ void __launch_bounds__(128) kB(const float* __restrict__ z) {
    __shared__ __align__(16) float scn[CHUNK * D];  // 32 KB
    const int tid   = threadIdx.x;
    const int token = blockIdx.x * TOK_PER_BLK + tid;
    const int split = blockIdx.y;

    // load + normalize token vector into registers (packed f32x2)
    const float4* z4 = (const float4*)(z + token * D);
    float4 zr[16];
    float s = 0.f;
#pragma unroll
    for (int j = 0; j < 16; j++) {
        zr[j] = z4[j];
        s += zr[j].x * zr[j].x + zr[j].y * zr[j].y +
             zr[j].z * zr[j].z + zr[j].w * zr[j].w;
    }
    const float inv = 1.0f / fmaxf(sqrtf(s), 1e-12f);
    unsigned long long zp[32];
#pragma unroll
    for (int j = 0; j < 16; j++) {
        zp[2 * j]     = pack2(zr[j].x * inv, zr[j].y * inv);
        zp[2 * j + 1] = pack2(zr[j].z * inv, zr[j].w * inv);
    }

    float best = -1e30f;
    int   bidx = 0;
    const int code0 = split * CODES_PER_SPLIT;

    for (int ch = 0; ch < CODES_PER_SPLIT / CHUNK; ch++) {
        const int cbase = code0 + ch * CHUNK;
        __syncthreads();
        {   // stage CHUNK codes of cn into smem (coalesced)
            const float4* src = (const float4*)(g_cn + (size_t)cbase * D);
            float4* dst = (float4*)scn;
            for (int i = tid; i < CHUNK * D / 4; i += 128) dst[i] = src[i];
        }
        __syncthreads();

        const ulonglong2* s2 = (const ulonglong2*)scn;
        for (int c = 0; c < CHUNK; c++) {
            const ulonglong2* p = s2 + c * 16;
            unsigned long long a0 = 0ull, a1 = 0ull, a2 = 0ull, a3 = 0ull;
#pragma unroll
            for (int j = 0; j < 16; j += 2) {
                ulonglong2 w0 = p[j];
                ulonglong2 w1 = p[j + 1];
                a0 = fma2(zp[2 * j],     w0.x, a0);
                a1 = fma2(zp[2 * j + 1], w0.y, a1);
                a2 = fma2(zp[2 * j + 2], w1.x, a2);
                a3 = fma2(zp[2 * j + 3], w1.y, a3);
            }
            unsigned long long t = add2(add2(a0, a1), add2(a2, a3));
            float lo = __uint_as_float((unsigned)t);
            float hi = __uint_as_float((unsigned)(t >> 32));
            float dot = lo + hi;
            if (dot > best) { best = dot; bidx = cbase + c; }
        }
    }
    g_bestval[split * BT + token] = best;
    g_bestidx[split * BT + token] = bidx;
}

// ---------------- Kernel B2: merge splits, emit idx ----------------
__global__ void kB2(float* __restrict__ out, int out_size) {
    int t = blockIdx.x * 256 + threadIdx.x;
    float best = g_bestval[t];
    int   bi   = g_bestidx[t];
#pragma unroll
    for (int sp = 1; sp < NSPLIT; sp++) {
        float v = g_bestval[sp * BT + t];
        if (v > best) { best = v; bi = g_bestidx[sp * BT + t]; }
    }
    g_idx[t] = bi;
    int off = BT * D + 1 + t;
    if (off < out_size) out[off] = (float)bi;
}

// ---------------- Kernel C: gather quantized + partial MSE sums ----------
__global__ void __launch_bounds__(256) kC(const float* __restrict__ z,
                                          float* __restrict__ out,
                                          int out_size) {
    __shared__ float red[256];
    const int tid = threadIdx.x;
    const float4* z4 = (const float4*)z;
    const float4* q4 = (const float4*)g_qcb;
    float4* o4 = (float4*)out;

    float ps = 0.f;
#pragma unroll
    for (int i = 0; i < 8; i++) {
        int g = blockIdx.x * 2048 + i * 256 + tid;     // 128 blks * 2048 = 262144 float4
        int token = g >> 4;
        int idx = g_idx[token];
        float4 q = q4[idx * 16 + (g & 15)];
        float4 zz = z4[g];
        if (g * 4 + 3 < out_size) o4[g] = q;
        float dx = q.x - zz.x, dy = q.y - zz.y;
        float dz_ = q.z - zz.z, dw = q.w - zz.w;
        ps += dx * dx + dy * dy + dz_ * dz_ + dw * dw;
    }
    red[tid] = ps;
    __syncthreads();
    for (int st = 128; st > 0; st >>= 1) {
        if (tid < st) red[tid] += red[tid + st];
        __syncthreads();
    }
    if (tid == 0) g_partials[blockIdx.x] = red[0];
}

// ---------------- Kernel D: finalize loss ----------------
__global__ void kD(float* __restrict__ out, int out_size) {
    __shared__ float red[128];
    int tid = threadIdx.x;
    red[tid] = g_partials[tid];
    __syncthreads();
    for (int st = 64; st > 0; st >>= 1) {
        if (tid < st) red[tid] += red[tid + st];
        __syncthreads();
    }
    if (tid == 0) {
        float loss = 1.25f * red[0] / (float)(BT * D);  // (1 + BETA) * mse
        if (BT * D < out_size) out[BT * D] = loss;
    }
}

// ---------------- launch ----------------
extern "C" void kernel_launch(void* const* d_in, const int* in_sizes, int n_in,
                              void* d_out, int out_size) {
    const float* z  = (const float*)d_in[0];
    const float* cb = (const float*)d_in[1];
    const float* pw = (const float*)d_in[2];
    const float* pb = (const float*)d_in[3];
    // d_in[4] = scale: positive constant, cannot change argmin or any output value.
    float* out = (float*)d_out;

    kA<<<NUM_EMB / 64, 256>>>(cb, pw, pb);
    dim3 gB(BT / TOK_PER_BLK, NSPLIT);
    kB<<<gB, 128>>>(z);
    kB2<<<BT / 256, 256>>>(out, out_size);
    kC<<<128, 256>>>(z, out, out_size);
    kD<<<1, 128>>>(out, out_size);
}

// round 3
// speedup vs baseline: 3.3659x; 3.3659x over previous
#include <cuda_runtime.h>
#include <cuda_fp16.h>
#include <cstdint>

#define NUM_EMB 16384
#define BT      16384
#define D       64
#define N_TILE  128
#define NTILES  (NUM_EMB / N_TILE)     // 128
#define M_TILE  128
#define NCTA    (BT / M_TILE)          // 128
#define INV2048 (4.8828125e-4f)

// smem: A tokens [128 x 256B], B double buffer [2 x 128 x 256B]
#define SM_A   0
#define SM_B0  32768
#define SM_B1  65536
#define SM_TOT 98304

// ---------------- device scratch ----------------
__device__ float  g_qcb[NUM_EMB * D];      // projected codebook (fp32, for gather)
__device__ __half g_cbh[NUM_EMB * 128];    // per code: [hi(64) | lo*2048 (64)] fp16
__device__ int    g_idx[BT];
__device__ float  g_partials[128];

// ---------------- helpers ----------------
__device__ __forceinline__ uint32_t smem_u32(const void* p) {
    uint32_t a;
    asm("{ .reg .u64 t; cvta.to.shared.u64 t, %1; cvt.u32.u64 %0, t; }" : "=r"(a) : "l"(p));
    return a;
}
// 16B-chunk XOR swizzle within a 256B row
__device__ __forceinline__ uint32_t swz(uint32_t byte, uint32_t row) {
    return ((((byte) >> 4) ^ (row & 7u)) << 4) | (byte & 15u);
}

#define LDSM_X4(r0, r1, r2, r3, addr) \
    asm volatile("ldmatrix.sync.aligned.m8n8.x4.shared.b16 {%0,%1,%2,%3}, [%4];" \
                 : "=r"(r0), "=r"(r1), "=r"(r2), "=r"(r3) : "r"(addr))

#define MMA16816(c0, c1, c2, c3, a0, a1, a2, a3, b0, b1) \
    asm volatile("mma.sync.aligned.m16n8k16.row.col.f32.f16.f16.f32 " \
                 "{%0,%1,%2,%3}, {%4,%5,%6,%7}, {%8,%9}, {%0,%1,%2,%3};" \
                 : "+f"(c0), "+f"(c1), "+f"(c2), "+f"(c3) \
                 : "r"(a0), "r"(a1), "r"(a2), "r"(a3), "r"(b0), "r"(b1))

#define CP_ASYNC16(dst, src) \
    asm volatile("cp.async.cg.shared.global [%0], [%1], 16;" :: "r"(dst), "l"(src) : "memory")
#define CP_COMMIT()  asm volatile("cp.async.commit_group;" ::: "memory")
#define CP_WAIT1()   asm volatile("cp.async.wait_group 1;" ::: "memory")
#define CP_WAIT0()   asm volatile("cp.async.wait_group 0;" ::: "memory")

// ================= kPrep: project + normalize + fp16 hi/lo split =================
__global__ void __launch_bounds__(256) kPrep(const float* __restrict__ cb,
                                             const float* __restrict__ pw,
                                             const float* __restrict__ pb) {
    __shared__ float pwT[64 * 64];
    __shared__ float qs [64 * 64];
    __shared__ float rnorm[64];
    const int tid = threadIdx.x;

    for (int i = tid; i < 4096; i += 256) {
        int c = i >> 6, k = i & 63;
        pwT[k * 64 + c] = pw[i];
    }
    __syncthreads();

    const int c  = tid & 63;
    const int rg = tid >> 6;
    const float bias = pb[c];
    for (int rr = 0; rr < 16; rr++) {
        int lrow = rg * 16 + rr;
        int row  = blockIdx.x * 64 + lrow;
        const float* cbr = cb + row * 64;
        float acc = bias;
#pragma unroll
        for (int k = 0; k < 64; k++)
            acc = fmaf(__ldg(cbr + k), pwT[k * 64 + c], acc);
        qs[lrow * 64 + c] = acc;
    }
    __syncthreads();

    if (tid < 64) {
        float s = 0.f;
#pragma unroll
        for (int k = 0; k < 64; k++) {
            float v = qs[tid * 64 + k];
            s = fmaf(v, v, s);
        }
        rnorm[tid] = 1.0f / fmaxf(sqrtf(s), 1e-12f);
    }
    __syncthreads();

    const int base = blockIdx.x * 4096;
    for (int i = tid; i < 4096; i += 256) {
        float v = qs[i];
        int row = i >> 6, col = i & 63;
        g_qcb[base + i] = v;
        float cn = v * rnorm[row];
        __half hi = __float2half_rn(cn);
        float lof = (cn - __half2float(hi)) * 2048.0f;
        size_t code = (size_t)(blockIdx.x * 64 + row);
        g_cbh[code * 128 + col]      = hi;
        g_cbh[code * 128 + 64 + col] = __float2half_rn(lof);
    }
}

// ================= kMain: HMMA GEMM + fused argmax =================
// 128 CTAs x 256 threads. CTA owns 128 tokens; loops 128 code-tiles of 128.
__global__ void __launch_bounds__(256, 1) kMain(const float* __restrict__ z,
                                                float* __restrict__ out, int out_size) {
    extern __shared__ char smem[];
    const uint32_t sb = smem_u32(smem);
    const int tid  = threadIdx.x;
    const int lane = tid & 31;
    const int w    = tid >> 5;

    // ---- token prep: normalize + hi/lo split into swizzled smem A ----
    if (tid < 128) {
        const int token = blockIdx.x * M_TILE + tid;
        const float4* z4 = (const float4*)(z + (size_t)token * D);
        float v[64];
        float s = 0.f;
#pragma unroll
        for (int j = 0; j < 16; j++) {
            float4 t = z4[j];
            v[4 * j] = t.x; v[4 * j + 1] = t.y; v[4 * j + 2] = t.z; v[4 * j + 3] = t.w;
            s += t.x * t.x + t.y * t.y + t.z * t.z + t.w * t.w;
        }
        const float inv = 1.0f / fmaxf(sqrtf(s), 1e-12f);
        const uint32_t rowbase = (uint32_t)tid * 256u;
#pragma unroll
        for (int j = 0; j < 32; j++) {
            float z0 = v[2 * j] * inv, z1 = v[2 * j + 1] * inv;
            __half h0 = __float2half_rn(z0), h1 = __float2half_rn(z1);
            float l0 = (z0 - __half2float(h0)) * 2048.0f;
            float l1 = (z1 - __half2float(h1)) * 2048.0f;
            __half2 hh = __halves2half2(h0, h1);
            __half2 ll = __halves2half2(__float2half_rn(l0), __float2half_rn(l1));
            uint32_t bh = 4u * j;          // hi bytes 0..127
            uint32_t bl = 128u + 4u * j;   // lo bytes 128..255
            *(__half2*)(smem + SM_A + rowbase + swz(bh, (uint32_t)tid)) = hh;
            *(__half2*)(smem + SM_A + rowbase + swz(bl, (uint32_t)tid)) = ll;
        }
    }

    // ---- B tile fill macro: 128 codes x 256B, 16B chunks, swizzled ----
#define FILL(stage, tile_)                                                        \
    do {                                                                          \
        for (int i = 0; i < 8; i++) {                                             \
            int idx = tid + i * 256;             /* 0..2047 */                    \
            uint32_t code = (uint32_t)idx >> 4;                                   \
            uint32_t ch   = (uint32_t)idx & 15u;                                  \
            uint32_t dst  = sb + (stage) + code * 256u + ((ch ^ (code & 7u)) << 4); \
            const __half* src = g_cbh + ((size_t)(tile_) * N_TILE + code) * 128 + ch * 8; \
            CP_ASYNC16(dst, src);                                                 \
        }                                                                         \
        CP_COMMIT();                                                              \
    } while (0)

    FILL(SM_B0, 0);
    FILL(SM_B1, 1);
    __syncthreads();   // token prep visible

    // ---- load A fragments (persistent in registers) ----
    uint32_t ah[16], al[16];
    {
        const uint32_t arow = (uint32_t)(w * 16) + (uint32_t)((lane & 7) + ((lane >> 3) & 1) * 8);
        const uint32_t kx   = (uint32_t)(lane >> 4) * 16u;
        const uint32_t abase = sb + SM_A + arow * 256u;
#pragma unroll
        for (int j = 0; j < 4; j++) {
            uint32_t adh = abase + swz(32u * j + kx, arow);
            LDSM_X4(ah[4 * j], ah[4 * j + 1], ah[4 * j + 2], ah[4 * j + 3], adh);
            uint32_t adl = abase + swz(128u + 32u * j + kx, arow);
            LDSM_X4(al[4 * j], al[4 * j + 1], al[4 * j + 2], al[4 * j + 3], adl);
        }
    }

    float best0 = -3.0f, best1 = -3.0f;
    int   bidx0 = 0,     bidx1 = 0;

    const uint32_t brow_in = (uint32_t)(lane & 7);
    const uint32_t bkx     = (uint32_t)(lane >> 3) * 16u;

    for (int t = 0; t < NTILES; t++) {
        if (t + 1 < NTILES) { CP_WAIT1(); } else { CP_WAIT0(); }
        __syncthreads();
        const uint32_t Bb = sb + ((t & 1) ? SM_B1 : SM_B0);

        for (int nb = 0; nb < 16; nb++) {
            const uint32_t brow = (uint32_t)(nb * 8) + brow_in;
            const uint32_t bbase = Bb + brow * 256u;
            uint32_t bh[8], bl[8];
            LDSM_X4(bh[0], bh[1], bh[2], bh[3], bbase + swz(0u   + bkx, brow));
            LDSM_X4(bh[4], bh[5], bh[6], bh[7], bbase + swz(64u  + bkx, brow));
            LDSM_X4(bl[0], bl[1], bl[2], bl[3], bbase + swz(128u + bkx, brow));
            LDSM_X4(bl[4], bl[5], bl[6], bl[7], bbase + swz(192u + bkx, brow));

            float c0 = 0.f, c1 = 0.f, c2 = 0.f, c3 = 0.f;   // hi*hi
            float x0 = 0.f, x1 = 0.f, x2 = 0.f, x3 = 0.f;   // cross (scaled 2048)
#pragma unroll
            for (int j = 0; j < 4; j++) {
                MMA16816(c0, c1, c2, c3, ah[4*j], ah[4*j+1], ah[4*j+2], ah[4*j+3], bh[2*j], bh[2*j+1]);
                MMA16816(x0, x1, x2, x3, ah[4*j], ah[4*j+1], ah[4*j+2], ah[4*j+3], bl[2*j], bl[2*j+1]);
                MMA16816(x0, x1, x2, x3, al[4*j], al[4*j+1], al[4*j+2], al[4*j+3], bh[2*j], bh[2*j+1]);
            }
            float v0 = fmaf(x0, INV2048, c0);
            float v1 = fmaf(x1, INV2048, c1);
            float v2 = fmaf(x2, INV2048, c2);
            float v3 = fmaf(x3, INV2048, c3);

            const int n0 = t * N_TILE + nb * 8 + (lane & 3) * 2;
            if (v0 > best0) { best0 = v0; bidx0 = n0; }
            if (v1 > best0) { best0 = v1; bidx0 = n0 + 1; }
            if (v2 > best1) { best1 = v2; bidx1 = n0; }
            if (v3 > best1) { best1 = v3; bidx1 = n0 + 1; }
        }
        __syncthreads();
        if (t + 2 < NTILES) FILL(((t & 1) ? SM_B1 : SM_B0), t + 2);
    }
#undef FILL

    // ---- reduce argmax across the 4 lanes of each row quad ----
#pragma unroll
    for (int off = 1; off < 4; off <<= 1) {
        float ob = __shfl_xor_sync(0xFFFFFFFFu, best0, off);
        int   oi = __shfl_xor_sync(0xFFFFFFFFu, bidx0, off);
        if (ob > best0 || (ob == best0 && oi < bidx0)) { best0 = ob; bidx0 = oi; }
        ob = __shfl_xor_sync(0xFFFFFFFFu, best1, off);
        oi = __shfl_xor_sync(0xFFFFFFFFu, bidx1, off);
        if (ob > best1 || (ob == best1 && oi < bidx1)) { best1 = ob; bidx1 = oi; }
    }
    if ((lane & 3) == 0) {
        const int tok0 = blockIdx.x * M_TILE + w * 16 + (lane >> 2);
        const int tok1 = tok0 + 8;
        g_idx[tok0] = bidx0;
        g_idx[tok1] = bidx1;
        int off0 = BT * D + 1 + tok0;
        int off1 = BT * D + 1 + tok1;
        if (off0 < out_size) out[off0] = (float)bidx0;
        if (off1 < out_size) out[off1] = (float)bidx1;
    }
}

// ================= kC: gather quantized + partial MSE =================
__global__ void __launch_bounds__(256) kC(const float* __restrict__ z,
                                          float* __restrict__ out, int out_size) {
    __shared__ float red[256];
    const int tid = threadIdx.x;
    const float4* z4 = (const float4*)z;
    const float4* q4 = (const float4*)g_qcb;
    float4* o4 = (float4*)out;

    float ps = 0.f;
#pragma unroll
    for (int i = 0; i < 8; i++) {
        int g = blockIdx.x * 2048 + i * 256 + tid;
        int token = g >> 4;
        int idx = g_idx[token];
        float4 q = q4[idx * 16 + (g & 15)];
        float4 zz = z4[g];
        if (g * 4 + 3 < out_size) o4[g] = q;
        float dx = q.x - zz.x, dy = q.y - zz.y;
        float dz_ = q.z - zz.z, dw = q.w - zz.w;
        ps += dx * dx + dy * dy + dz_ * dz_ + dw * dw;
    }
    red[tid] = ps;
    __syncthreads();
    for (int st = 128; st > 0; st >>= 1) {
        if (tid < st) red[tid] += red[tid + st];
        __syncthreads();
    }
    if (tid == 0) g_partials[blockIdx.x] = red[0];
}

// ================= kD: finalize loss =================
__global__ void kD(float* __restrict__ out, int out_size) {
    __shared__ float red[128];
    int tid = threadIdx.x;
    red[tid] = g_partials[tid];
    __syncthreads();
    for (int st = 64; st > 0; st >>= 1) {
        if (tid < st) red[tid] += red[tid + st];
        __syncthreads();
    }
    if (tid == 0) {
        float loss = 1.25f * red[0] / (float)(BT * D);
        if (BT * D < out_size) out[BT * D] = loss;
    }
}

// ================= launch =================
extern "C" void kernel_launch(void* const* d_in, const int* in_sizes, int n_in,
                              void* d_out, int out_size) {
    const float* z  = (const float*)d_in[0];
    const float* cb = (const float*)d_in[1];
    const float* pw = (const float*)d_in[2];
    const float* pb = (const float*)d_in[3];
    // d_in[4] = scale: positive constant, cannot change argmin or any output value.
    float* out = (float*)d_out;

    cudaFuncSetAttribute(kMain, cudaFuncAttributeMaxDynamicSharedMemorySize, SM_TOT);

    kPrep<<<NUM_EMB / 64, 256>>>(cb, pw, pb);
    kMain<<<NCTA, 256, SM_TOT>>>(z, out, out_size);
    kC<<<128, 256>>>(z, out, out_size);
    kD<<<1, 128>>>(out, out_size);
}